// round 8
// baseline (speedup 1.0000x reference)
#include <cuda_runtime.h>
#include <cuda_bf16.h>
#include <cuda_fp16.h>
#include <cstdint>

#define BB 256
#define MM 80
#define TT 1000
#define HH 128
#define GG 384
#define TPAD 1024

// ---------------- device scratch ----------------
__device__ float g_gx[(size_t)BB * TT * GG];                // 393 MB
__device__ __nv_bfloat16 g_xhi[(size_t)BB * TPAD * MM];     // 42 MB
__device__ __nv_bfloat16 g_xlo[(size_t)BB * TPAD * MM];     // 42 MB

// ---------------- helpers ----------------
__device__ __forceinline__ float fast_sigmoid(float x) {
    float e = __expf(-x);
    return __fdividef(1.0f, 1.0f + e);
}
__device__ __forceinline__ float fast_tanh(float x) {
    float ax = fabsf(x);
    float e = __expf(-2.0f * ax);
    float t = __fdividef(1.0f - e, 1.0f + e);
    return copysignf(t, x);
}
__device__ __forceinline__ void cp16(uint32_t saddr, const void* g) {
    asm volatile("cp.async.cg.shared.global [%0], [%1], 16;" :: "r"(saddr), "l"(g));
}
__device__ __forceinline__ void cp_commit() { asm volatile("cp.async.commit_group;" ::: "memory"); }
__device__ __forceinline__ void cp_wait0()  { asm volatile("cp.async.wait_group 0;" ::: "memory"); }
__device__ __forceinline__ uint32_t smem_u32(const void* p) {
    uint32_t a;
    asm("{ .reg .u64 t; cvta.to.shared.u64 t, %1; cvt.u32.u64 %0, t; }" : "=r"(a) : "l"(p));
    return a;
}
// bf16 mma (gx kernel)
__device__ __forceinline__ void mma16816(float* c, uint32_t a0, uint32_t a1,
                                         uint32_t a2, uint32_t a3,
                                         uint32_t b0, uint32_t b1) {
    asm("mma.sync.aligned.m16n8k16.row.col.f32.bf16.bf16.f32 "
        "{%0,%1,%2,%3}, {%4,%5,%6,%7}, {%8,%9}, {%0,%1,%2,%3};"
        : "+f"(c[0]), "+f"(c[1]), "+f"(c[2]), "+f"(c[3])
        : "r"(a0), "r"(a1), "r"(a2), "r"(a3), "r"(b0), "r"(b1));
}
// fp16 mma (gru kernel)
__device__ __forceinline__ void mma16816h(float* c, uint32_t a0, uint32_t a1,
                                          uint32_t a2, uint32_t a3,
                                          uint32_t b0, uint32_t b1) {
    asm("mma.sync.aligned.m16n8k16.row.col.f32.f16.f16.f32 "
        "{%0,%1,%2,%3}, {%4,%5,%6,%7}, {%8,%9}, {%0,%1,%2,%3};"
        : "+f"(c[0]), "+f"(c[1]), "+f"(c[2]), "+f"(c[3])
        : "r"(a0), "r"(a1), "r"(a2), "r"(a3), "r"(b0), "r"(b1));
}
__device__ __forceinline__ uint32_t bf16_hi_pack(float a, float b) {
    uint32_t ua = (uint32_t)__bfloat16_as_ushort(__float2bfloat16(a));
    uint32_t ub = (uint32_t)__bfloat16_as_ushort(__float2bfloat16(b));
    return ua | (ub << 16);
}
__device__ __forceinline__ uint32_t bf16_lo_pack(float a, float b) {
    float ra = a - __bfloat162float(__float2bfloat16(a));
    float rb = b - __bfloat162float(__float2bfloat16(b));
    return bf16_hi_pack(ra, rb);
}
__device__ __forceinline__ uint32_t f16_pack(float a, float b) {
    __half2 p = __floats2half2_rn(a, b);
    return reinterpret_cast<uint32_t&>(p);
}
__device__ __forceinline__ uint32_t f16_lo_pack(float a, float b) {
    float ra = a - __half2float(__float2half_rn(a));
    float rb = b - __half2float(__float2half_rn(b));
    return f16_pack(ra, rb);
}

// ================= prep: transpose + bf16 split =================
#define PREP_THREADS 256
__global__ __launch_bounds__(PREP_THREADS)
void prep_kernel(const float* __restrict__ x)
{
    __shared__ float xs[MM][129];
    const int b = blockIdx.y, t0 = blockIdx.x * 128;
    const int tid = threadIdx.x;

    for (int idx = tid; idx < MM * 128; idx += PREP_THREADS) {
        int m = idx >> 7, j = idx & 127;
        int t = t0 + j;
        xs[m][j] = (t < TT) ? x[((size_t)b * MM + m) * TT + t] : 0.0f;
    }
    __syncthreads();

    for (int idx = tid; idx < 128 * 10; idx += PREP_THREADS) {
        int j = idx / 10, mv = idx % 10;
        int m0 = mv * 8;
        __align__(16) __nv_bfloat16 hi[8];
        __align__(16) __nv_bfloat16 lo[8];
        #pragma unroll
        for (int u = 0; u < 8; u++) {
            float v = xs[m0 + u][j];
            __nv_bfloat16 h = __float2bfloat16(v);
            hi[u] = h;
            lo[u] = __float2bfloat16(v - __bfloat162float(h));
        }
        size_t off = ((size_t)b * TPAD + t0 + j) * MM + m0;
        *(uint4*)(g_xhi + off) = *(const uint4*)hi;
        *(uint4*)(g_xlo + off) = *(const uint4*)lo;
    }
}

// ================= gx via mma.sync HMMA (split-bf16, 3 terms) =================
#define GXT 256
#define A_PITCH 88
#define W_PITCH 84
#define SM_AHI 0
#define SM_ALO (128 * A_PITCH * 2)
#define SM_WHI (SM_ALO + 128 * A_PITCH * 2)
#define SM_WLO (SM_WHI + 192 * W_PITCH * 2)
#define GX_SMEM (SM_WLO + 192 * W_PITCH * 2)

__device__ __forceinline__ uint32_t lds_pair(const char* base, int row, int col, int pitch) {
    return *(const uint32_t*)(base + (size_t)(row * pitch + col) * 2);
}

__global__ __launch_bounds__(GXT)
void gx_hmma_kernel(const float* __restrict__ W_ih)
{
    extern __shared__ char sm[];
    const int tid = threadIdx.x;
    const int lane = tid & 31;
    const int w = tid >> 5;
    const int grp = lane >> 2;
    const int q = lane & 3;
    const int tt = blockIdx.x >> 1;
    const int ghalf = blockIdx.x & 1;
    const int gbase = ghalf * 192;
    const int b = blockIdx.y;
    const uint32_t sb = smem_u32(sm);

    for (int i = tid; i < 2560; i += GXT) {
        int split = i / 1280;
        int rem = i - split * 1280;
        int row = rem / 10, ch = rem - row * 10;
        uint32_t dst = sb + (split ? SM_ALO : SM_AHI) + row * (A_PITCH * 2) + ch * 16;
        const __nv_bfloat16* src = (split ? g_xlo : g_xhi)
            + ((size_t)b * TPAD + tt * 128 + row) * MM + ch * 8;
        cp16(dst, src);
    }
    cp_commit();

    for (int i = tid; i < 192 * MM; i += GXT) {
        int g = i / MM, m = i - g * MM;
        float v = W_ih[(size_t)(gbase + g) * MM + m];
        __nv_bfloat16 h = __float2bfloat16(v);
        __nv_bfloat16 l = __float2bfloat16(v - __bfloat162float(h));
        *(__nv_bfloat16*)(sm + SM_WHI + (size_t)(g * W_PITCH + m) * 2) = h;
        *(__nv_bfloat16*)(sm + SM_WLO + (size_t)(g * W_PITCH + m) * 2) = l;
    }
    cp_wait0();
    __syncthreads();

    const int r0 = w * 16 + grp;
    uint32_t ahi[20], alo[20];
    #pragma unroll
    for (int ks = 0; ks < 5; ks++) {
        int c = 16 * ks + 2 * q;
        ahi[4 * ks + 0] = lds_pair(sm + SM_AHI, r0,     c,     A_PITCH);
        ahi[4 * ks + 1] = lds_pair(sm + SM_AHI, r0 + 8, c,     A_PITCH);
        ahi[4 * ks + 2] = lds_pair(sm + SM_AHI, r0,     c + 8, A_PITCH);
        ahi[4 * ks + 3] = lds_pair(sm + SM_AHI, r0 + 8, c + 8, A_PITCH);
        alo[4 * ks + 0] = lds_pair(sm + SM_ALO, r0,     c,     A_PITCH);
        alo[4 * ks + 1] = lds_pair(sm + SM_ALO, r0 + 8, c,     A_PITCH);
        alo[4 * ks + 2] = lds_pair(sm + SM_ALO, r0,     c + 8, A_PITCH);
        alo[4 * ks + 3] = lds_pair(sm + SM_ALO, r0 + 8, c + 8, A_PITCH);
    }

    const int trow = tt * 128 + w * 16 + grp;
    float* dst = g_gx + ((size_t)b * TT + trow) * GG + gbase;
    float* dst8 = dst + 8 * GG;
    const bool v0 = (trow < TT);
    const bool v8 = (trow + 8 < TT);

    for (int gp = 0; gp < 12; gp++) {
        float acc0[4] = {0.f, 0.f, 0.f, 0.f};
        float acc1[4] = {0.f, 0.f, 0.f, 0.f};
        const int gA = gp * 16 + grp;
        const int gB = gp * 16 + 8 + grp;
        #pragma unroll
        for (int ks = 0; ks < 5; ks++) {
            int c = 16 * ks + 2 * q;
            uint32_t bh0a = lds_pair(sm + SM_WHI, gA, c,     W_PITCH);
            uint32_t bh0b = lds_pair(sm + SM_WHI, gA, c + 8, W_PITCH);
            uint32_t bh1a = lds_pair(sm + SM_WHI, gB, c,     W_PITCH);
            uint32_t bh1b = lds_pair(sm + SM_WHI, gB, c + 8, W_PITCH);
            mma16816(acc0, ahi[4*ks], ahi[4*ks+1], ahi[4*ks+2], ahi[4*ks+3], bh0a, bh0b);
            mma16816(acc1, ahi[4*ks], ahi[4*ks+1], ahi[4*ks+2], ahi[4*ks+3], bh1a, bh1b);
            mma16816(acc0, alo[4*ks], alo[4*ks+1], alo[4*ks+2], alo[4*ks+3], bh0a, bh0b);
            mma16816(acc1, alo[4*ks], alo[4*ks+1], alo[4*ks+2], alo[4*ks+3], bh1a, bh1b);
            uint32_t bl0a = lds_pair(sm + SM_WLO, gA, c,     W_PITCH);
            uint32_t bl0b = lds_pair(sm + SM_WLO, gA, c + 8, W_PITCH);
            uint32_t bl1a = lds_pair(sm + SM_WLO, gB, c,     W_PITCH);
            uint32_t bl1b = lds_pair(sm + SM_WLO, gB, c + 8, W_PITCH);
            mma16816(acc0, ahi[4*ks], ahi[4*ks+1], ahi[4*ks+2], ahi[4*ks+3], bl0a, bl0b);
            mma16816(acc1, ahi[4*ks], ahi[4*ks+1], ahi[4*ks+2], ahi[4*ks+3], bl1a, bl1b);
        }
        const int col0 = gp * 16 + 2 * q;
        if (v0) {
            *(float2*)(dst + col0)     = make_float2(acc0[0], acc0[1]);
            *(float2*)(dst + col0 + 8) = make_float2(acc1[0], acc1[1]);
        }
        if (v8) {
            *(float2*)(dst8 + col0)     = make_float2(acc0[2], acc0[3]);
            *(float2*)(dst8 + col0 + 8) = make_float2(acc1[2], acc1[3]);
        }
    }
}

// ================= gru: warp-specialized fp16 HMMA, 2 staggered groups =======
// 32 blocks x 640 threads. Warps 0..11: mma (2 m-tiles each, W fp16 in 64 regs).
// Warps 12..19 (256 thr): gates — batch gb (0..3) of the active group, j-pair jp.
// Groups: A = b0..b0+3, B = b0+4..b0+7. Per t:
//   phase1: mma gh_B(t) from hb_B   |  gates A: h_A <- gate(ghs_A, gx_A(t))
//   phase2: mma gh_A(t+1) from hb_A |  gates B: h_B <- gate(ghs_B, gx_B(t))
// n=8 B-fragment columns = [h_hi b0..3 | h_lo b0..3] (fp16 split of h).
#define GRUT 640

__global__ __launch_bounds__(GRUT, 1)
void gru_hmma_kernel(const float* __restrict__ W_hh,
                     const float* __restrict__ b_ih,
                     const float* __restrict__ b_hh,
                     float* __restrict__ out)
{
    __shared__ uint32_t hbA_w[8 * 136];      // u64[8][68] view
    __shared__ uint32_t hbB_w[8 * 136];
    __shared__ float ghsA[8 * 388];
    __shared__ float ghsB[8 * 388];

    const int tid = threadIdx.x;
    const int lane = tid & 31;
    const int wid = tid >> 5;
    const int grp = lane >> 2;
    const int q = lane & 3;
    const int b0 = blockIdx.x * 8;
    const bool is_mma = (wid < 12);

    // ---- mma-warp W fragments (fp16) ----
    uint32_t whi0[8][4], whi1[8][4];
    if (is_mma) {
        const int m0 = wid * 32;
        #pragma unroll
        for (int kt = 0; kt < 8; kt++) {
            #pragma unroll
            for (int r = 0; r < 4; r++) {
                int row = m0 + grp + (r & 1) * 8;
                int col = kt * 16 + 2 * q + (r >> 1) * 8;
                float f0 = __ldg(W_hh + (size_t)row * HH + col);
                float f1 = __ldg(W_hh + (size_t)row * HH + col + 1);
                whi0[kt][r] = f16_pack(f0, f1);
                float g0 = __ldg(W_hh + (size_t)(row + 16) * HH + col);
                float g1 = __ldg(W_hh + (size_t)(row + 16) * HH + col + 1);
                whi1[kt][r] = f16_pack(g0, g1);
            }
        }
    }
    // zero h buffers and ghsA (gh_A(0) = Whh*0 = 0)
    for (int i = tid; i < 8 * 136; i += GRUT) { hbA_w[i] = 0u; hbB_w[i] = 0u; }
    for (int i = tid; i < 8 * 388; i += GRUT) { ghsA[i] = 0.0f; }

    // ---- gate-warp setup ----
    const int gt = tid - 384;                // 0..255 for gate warps
    const int gb = (gt >> 6) & 3;
    const int jp = gt & 63;
    const int j = 2 * jp;
    const int ktj = jp >> 3, uj = jp & 7;
    const int slot = (uj < 4) ? (2 * (ktj * 8 + uj)) : (2 * (ktj * 8 + (uj - 4)) + 1);
    const int hi_word = gb * 136 + slot;
    const int lo_word = (gb + 4) * 136 + slot;

    float br0 = 0.f, br1 = 0.f, bz0 = 0.f, bz1 = 0.f;
    float bin0 = 0.f, bin1 = 0.f, bhn0 = 0.f, bhn1 = 0.f;
    float hA0 = 0.f, hA1 = 0.f, hB0 = 0.f, hB1 = 0.f;
    const float* gxpA = g_gx + ((size_t)(b0 + (gb & 3)) * TT) * GG + j;
    const float* gxpB = g_gx + ((size_t)(b0 + 4 + (gb & 3)) * TT) * GG + j;
    float2 crA = make_float2(0.f, 0.f), czA = crA, cnA = crA;
    float2 crB = crA, czB = crA, cnB = crA;
    if (!is_mma) {
        br0 = b_ih[j] + b_hh[j];
        br1 = b_ih[j + 1] + b_hh[j + 1];
        bz0 = b_ih[HH + j] + b_hh[HH + j];
        bz1 = b_ih[HH + j + 1] + b_hh[HH + j + 1];
        bin0 = b_ih[2 * HH + j];     bhn0 = b_hh[2 * HH + j];
        bin1 = b_ih[2 * HH + j + 1]; bhn1 = b_hh[2 * HH + j + 1];
        crA = __ldg((const float2*)(gxpA));
        czA = __ldg((const float2*)(gxpA + HH));
        cnA = __ldg((const float2*)(gxpA + 2 * HH));
        crB = __ldg((const float2*)(gxpB));
        czB = __ldg((const float2*)(gxpB + HH));
        cnB = __ldg((const float2*)(gxpB + 2 * HH));
    }
    __syncthreads();

    const unsigned long long* hbA64 = (const unsigned long long*)hbA_w;
    const unsigned long long* hbB64 = (const unsigned long long*)hbB_w;
    const int m0 = wid * 32;

    for (int t = 0; t < TT; t++) {
        const size_t tn = (t + 1 < TT) ? (size_t)(t + 1) : (size_t)t;

        // ================= phase 1: mma gh_B | gates A =================
        if (is_mma) {
            float C0[4] = {0.f, 0.f, 0.f, 0.f};
            float C1[4] = {0.f, 0.f, 0.f, 0.f};
            #pragma unroll
            for (int kt = 0; kt < 8; kt++) {
                unsigned long long bb = hbB64[grp * 68 + kt * 8 + q];
                uint32_t bv0 = (uint32_t)bb;
                uint32_t bv1 = (uint32_t)(bb >> 32);
                mma16816h(C0, whi0[kt][0], whi0[kt][1], whi0[kt][2], whi0[kt][3], bv0, bv1);
                mma16816h(C1, whi1[kt][0], whi1[kt][1], whi1[kt][2], whi1[kt][3], bv0, bv1);
            }
            ghsB[(2 * q)     * 388 + m0 + grp]          = C0[0];
            ghsB[(2 * q + 1) * 388 + m0 + grp]          = C0[1];
            ghsB[(2 * q)     * 388 + m0 + grp + 8]      = C0[2];
            ghsB[(2 * q + 1) * 388 + m0 + grp + 8]      = C0[3];
            ghsB[(2 * q)     * 388 + m0 + 16 + grp]     = C1[0];
            ghsB[(2 * q + 1) * 388 + m0 + 16 + grp]     = C1[1];
            ghsB[(2 * q)     * 388 + m0 + 16 + grp + 8] = C1[2];
            ghsB[(2 * q + 1) * 388 + m0 + 16 + grp + 8] = C1[3];
        } else {
            const float* gA = &ghsA[gb * 388];
            const float* gB = &ghsA[(gb + 4) * 388];
            float2 ra = *(const float2*)(gA + j);
            float2 rb = *(const float2*)(gB + j);
            float2 za = *(const float2*)(gA + HH + j);
            float2 zb = *(const float2*)(gB + HH + j);
            float2 na = *(const float2*)(gA + 2 * HH + j);
            float2 nb = *(const float2*)(gB + 2 * HH + j);
            float r0 = fast_sigmoid(crA.x + br0 + ra.x + rb.x);
            float r1 = fast_sigmoid(crA.y + br1 + ra.y + rb.y);
            float z0 = fast_sigmoid(czA.x + bz0 + za.x + zb.x);
            float z1 = fast_sigmoid(czA.y + bz1 + za.y + zb.y);
            float n0 = fast_tanh(cnA.x + bin0 + r0 * (na.x + nb.x + bhn0));
            float n1 = fast_tanh(cnA.y + bin1 + r1 * (na.y + nb.y + bhn1));
            hA0 = (1.0f - z0) * n0 + z0 * hA0;
            hA1 = (1.0f - z1) * n1 + z1 * hA1;
            hbA_w[hi_word] = f16_pack(hA0, hA1);
            hbA_w[lo_word] = f16_lo_pack(hA0, hA1);
            // prefetch gx_A(t+1) (consumed next iteration's phase 1)
            const float* pn = gxpA + tn * GG;
            crA = __ldg((const float2*)(pn));
            czA = __ldg((const float2*)(pn + HH));
            cnA = __ldg((const float2*)(pn + 2 * HH));
        }
        __syncthreads();

        // ================= phase 2: mma gh_A | gates B =================
        if (is_mma) {
            float C0[4] = {0.f, 0.f, 0.f, 0.f};
            float C1[4] = {0.f, 0.f, 0.f, 0.f};
            #pragma unroll
            for (int kt = 0; kt < 8; kt++) {
                unsigned long long bb = hbA64[grp * 68 + kt * 8 + q];
                uint32_t bv0 = (uint32_t)bb;
                uint32_t bv1 = (uint32_t)(bb >> 32);
                mma16816h(C0, whi0[kt][0], whi0[kt][1], whi0[kt][2], whi0[kt][3], bv0, bv1);
                mma16816h(C1, whi1[kt][0], whi1[kt][1], whi1[kt][2], whi1[kt][3], bv0, bv1);
            }
            ghsA[(2 * q)     * 388 + m0 + grp]          = C0[0];
            ghsA[(2 * q + 1) * 388 + m0 + grp]          = C0[1];
            ghsA[(2 * q)     * 388 + m0 + grp + 8]      = C0[2];
            ghsA[(2 * q + 1) * 388 + m0 + grp + 8]      = C0[3];
            ghsA[(2 * q)     * 388 + m0 + 16 + grp]     = C1[0];
            ghsA[(2 * q + 1) * 388 + m0 + 16 + grp]     = C1[1];
            ghsA[(2 * q)     * 388 + m0 + 16 + grp + 8] = C1[2];
            ghsA[(2 * q + 1) * 388 + m0 + 16 + grp + 8] = C1[3];
        } else {
            const float* gA = &ghsB[gb * 388];
            const float* gB = &ghsB[(gb + 4) * 388];
            float2 ra = *(const float2*)(gA + j);
            float2 rb = *(const float2*)(gB + j);
            float2 za = *(const float2*)(gA + HH + j);
            float2 zb = *(const float2*)(gB + HH + j);
            float2 na = *(const float2*)(gA + 2 * HH + j);
            float2 nb = *(const float2*)(gB + 2 * HH + j);
            float r0 = fast_sigmoid(crB.x + br0 + ra.x + rb.x);
            float r1 = fast_sigmoid(crB.y + br1 + ra.y + rb.y);
            float z0 = fast_sigmoid(czB.x + bz0 + za.x + zb.x);
            float z1 = fast_sigmoid(czB.y + bz1 + za.y + zb.y);
            float n0 = fast_tanh(cnB.x + bin0 + r0 * (na.x + nb.x + bhn0));
            float n1 = fast_tanh(cnB.y + bin1 + r1 * (na.y + nb.y + bhn1));
            hB0 = (1.0f - z0) * n0 + z0 * hB0;
            hB1 = (1.0f - z1) * n1 + z1 * hB1;
            hbB_w[hi_word] = f16_pack(hB0, hB1);
            hbB_w[lo_word] = f16_lo_pack(hB0, hB1);
            const float* pn = gxpB + tn * GG;
            crB = __ldg((const float2*)(pn));
            czB = __ldg((const float2*)(pn + HH));
            cnB = __ldg((const float2*)(pn + 2 * HH));
        }
        __syncthreads();
    }

    if (!is_mma) {
        *(float2*)(out + (size_t)(b0 + gb) * HH + j)     = make_float2(hA0, hA1);
        *(float2*)(out + (size_t)(b0 + 4 + gb) * HH + j) = make_float2(hB0, hB1);
    }
}

// ================= launch =================
extern "C" void kernel_launch(void* const* d_in, const int* in_sizes, int n_in,
                              void* d_out, int out_size)
{
    const float* x    = (const float*)d_in[0];
    const float* W_ih = (const float*)d_in[1];
    const float* W_hh = (const float*)d_in[2];
    const float* b_ih = (const float*)d_in[3];
    const float* b_hh = (const float*)d_in[4];
    float* out = (float*)d_out;

    cudaFuncSetAttribute(gx_hmma_kernel,
                         cudaFuncAttributeMaxDynamicSharedMemorySize, GX_SMEM);

    prep_kernel<<<dim3(8, BB), PREP_THREADS>>>(x);
    gx_hmma_kernel<<<dim3(16, BB), GXT, GX_SMEM>>>(W_ih);
    gru_hmma_kernel<<<BB / 8, GRUT>>>(W_hh, b_ih, b_hh, out);
}

// round 9
// speedup vs baseline: 1.9009x; 1.9009x over previous
#include <cuda_runtime.h>
#include <cuda_bf16.h>
#include <cuda_fp16.h>
#include <cstdint>

#define BB 256
#define MM 80
#define TT 1000
#define HH 128
#define GG 384
#define TPAD 1024

// ---------------- device scratch ----------------
__device__ float g_gx[(size_t)BB * TT * GG];                // 393 MB
__device__ __nv_bfloat16 g_xhi[(size_t)BB * TPAD * MM];     // 42 MB
__device__ __nv_bfloat16 g_xlo[(size_t)BB * TPAD * MM];     // 42 MB

// ---------------- helpers ----------------
__device__ __forceinline__ float fast_sigmoid(float x) {
    float e = __expf(-x);
    return __fdividef(1.0f, 1.0f + e);
}
__device__ __forceinline__ float fast_tanh(float x) {
    float ax = fabsf(x);
    float e = __expf(-2.0f * ax);
    float t = __fdividef(1.0f - e, 1.0f + e);
    return copysignf(t, x);
}
__device__ __forceinline__ void cp16(uint32_t saddr, const void* g) {
    asm volatile("cp.async.cg.shared.global [%0], [%1], 16;" :: "r"(saddr), "l"(g));
}
__device__ __forceinline__ void cp_commit() { asm volatile("cp.async.commit_group;" ::: "memory"); }
__device__ __forceinline__ void cp_wait0()  { asm volatile("cp.async.wait_group 0;" ::: "memory"); }
__device__ __forceinline__ uint32_t smem_u32(const void* p) {
    uint32_t a;
    asm("{ .reg .u64 t; cvta.to.shared.u64 t, %1; cvt.u32.u64 %0, t; }" : "=r"(a) : "l"(p));
    return a;
}
// bf16 mma (gx kernel)
__device__ __forceinline__ void mma16816(float* c, uint32_t a0, uint32_t a1,
                                         uint32_t a2, uint32_t a3,
                                         uint32_t b0, uint32_t b1) {
    asm("mma.sync.aligned.m16n8k16.row.col.f32.bf16.bf16.f32 "
        "{%0,%1,%2,%3}, {%4,%5,%6,%7}, {%8,%9}, {%0,%1,%2,%3};"
        : "+f"(c[0]), "+f"(c[1]), "+f"(c[2]), "+f"(c[3])
        : "r"(a0), "r"(a1), "r"(a2), "r"(a3), "r"(b0), "r"(b1));
}
// fp16 mma (gru kernel)
__device__ __forceinline__ void mma16816h(float* c, uint32_t a0, uint32_t a1,
                                          uint32_t a2, uint32_t a3,
                                          uint32_t b0, uint32_t b1) {
    asm("mma.sync.aligned.m16n8k16.row.col.f32.f16.f16.f32 "
        "{%0,%1,%2,%3}, {%4,%5,%6,%7}, {%8,%9}, {%0,%1,%2,%3};"
        : "+f"(c[0]), "+f"(c[1]), "+f"(c[2]), "+f"(c[3])
        : "r"(a0), "r"(a1), "r"(a2), "r"(a3), "r"(b0), "r"(b1));
}
__device__ __forceinline__ uint32_t f16_pack(float a, float b) {
    __half2 p = __floats2half2_rn(a, b);
    return reinterpret_cast<uint32_t&>(p);
}
__device__ __forceinline__ uint32_t f16_lo_pack(float a, float b) {
    float ra = a - __half2float(__float2half_rn(a));
    float rb = b - __half2float(__float2half_rn(b));
    return f16_pack(ra, rb);
}

// ================= prep: transpose + bf16 split =================
#define PREP_THREADS 256
__global__ __launch_bounds__(PREP_THREADS)
void prep_kernel(const float* __restrict__ x)
{
    __shared__ float xs[MM][129];
    const int b = blockIdx.y, t0 = blockIdx.x * 128;
    const int tid = threadIdx.x;

    for (int idx = tid; idx < MM * 128; idx += PREP_THREADS) {
        int m = idx >> 7, j = idx & 127;
        int t = t0 + j;
        xs[m][j] = (t < TT) ? x[((size_t)b * MM + m) * TT + t] : 0.0f;
    }
    __syncthreads();

    for (int idx = tid; idx < 128 * 10; idx += PREP_THREADS) {
        int j = idx / 10, mv = idx % 10;
        int m0 = mv * 8;
        __align__(16) __nv_bfloat16 hi[8];
        __align__(16) __nv_bfloat16 lo[8];
        #pragma unroll
        for (int u = 0; u < 8; u++) {
            float v = xs[m0 + u][j];
            __nv_bfloat16 h = __float2bfloat16(v);
            hi[u] = h;
            lo[u] = __float2bfloat16(v - __bfloat162float(h));
        }
        size_t off = ((size_t)b * TPAD + t0 + j) * MM + m0;
        *(uint4*)(g_xhi + off) = *(const uint4*)hi;
        *(uint4*)(g_xlo + off) = *(const uint4*)lo;
    }
}

// ================= gx via mma.sync HMMA (split-bf16, 3 terms) =================
#define GXT 256
#define A_PITCH 88
#define W_PITCH 84
#define SM_AHI 0
#define SM_ALO (128 * A_PITCH * 2)
#define SM_WHI (SM_ALO + 128 * A_PITCH * 2)
#define SM_WLO (SM_WHI + 192 * W_PITCH * 2)
#define GX_SMEM (SM_WLO + 192 * W_PITCH * 2)

__device__ __forceinline__ uint32_t lds_pair(const char* base, int row, int col, int pitch) {
    return *(const uint32_t*)(base + (size_t)(row * pitch + col) * 2);
}

__global__ __launch_bounds__(GXT)
void gx_hmma_kernel(const float* __restrict__ W_ih)
{
    extern __shared__ char sm[];
    const int tid = threadIdx.x;
    const int lane = tid & 31;
    const int w = tid >> 5;
    const int grp = lane >> 2;
    const int q = lane & 3;
    const int tt = blockIdx.x >> 1;
    const int ghalf = blockIdx.x & 1;
    const int gbase = ghalf * 192;
    const int b = blockIdx.y;
    const uint32_t sb = smem_u32(sm);

    for (int i = tid; i < 2560; i += GXT) {
        int split = i / 1280;
        int rem = i - split * 1280;
        int row = rem / 10, ch = rem - row * 10;
        uint32_t dst = sb + (split ? SM_ALO : SM_AHI) + row * (A_PITCH * 2) + ch * 16;
        const __nv_bfloat16* src = (split ? g_xlo : g_xhi)
            + ((size_t)b * TPAD + tt * 128 + row) * MM + ch * 8;
        cp16(dst, src);
    }
    cp_commit();

    for (int i = tid; i < 192 * MM; i += GXT) {
        int g = i / MM, m = i - g * MM;
        float v = W_ih[(size_t)(gbase + g) * MM + m];
        __nv_bfloat16 h = __float2bfloat16(v);
        __nv_bfloat16 l = __float2bfloat16(v - __bfloat162float(h));
        *(__nv_bfloat16*)(sm + SM_WHI + (size_t)(g * W_PITCH + m) * 2) = h;
        *(__nv_bfloat16*)(sm + SM_WLO + (size_t)(g * W_PITCH + m) * 2) = l;
    }
    cp_wait0();
    __syncthreads();

    const int r0 = w * 16 + grp;
    uint32_t ahi[20], alo[20];
    #pragma unroll
    for (int ks = 0; ks < 5; ks++) {
        int c = 16 * ks + 2 * q;
        ahi[4 * ks + 0] = lds_pair(sm + SM_AHI, r0,     c,     A_PITCH);
        ahi[4 * ks + 1] = lds_pair(sm + SM_AHI, r0 + 8, c,     A_PITCH);
        ahi[4 * ks + 2] = lds_pair(sm + SM_AHI, r0,     c + 8, A_PITCH);
        ahi[4 * ks + 3] = lds_pair(sm + SM_AHI, r0 + 8, c + 8, A_PITCH);
        alo[4 * ks + 0] = lds_pair(sm + SM_ALO, r0,     c,     A_PITCH);
        alo[4 * ks + 1] = lds_pair(sm + SM_ALO, r0 + 8, c,     A_PITCH);
        alo[4 * ks + 2] = lds_pair(sm + SM_ALO, r0,     c + 8, A_PITCH);
        alo[4 * ks + 3] = lds_pair(sm + SM_ALO, r0 + 8, c + 8, A_PITCH);
    }

    const int trow = tt * 128 + w * 16 + grp;
    float* dst = g_gx + ((size_t)b * TT + trow) * GG + gbase;
    float* dst8 = dst + 8 * GG;
    const bool v0 = (trow < TT);
    const bool v8 = (trow + 8 < TT);

    for (int gp = 0; gp < 12; gp++) {
        float acc0[4] = {0.f, 0.f, 0.f, 0.f};
        float acc1[4] = {0.f, 0.f, 0.f, 0.f};
        const int gA = gp * 16 + grp;
        const int gB = gp * 16 + 8 + grp;
        #pragma unroll
        for (int ks = 0; ks < 5; ks++) {
            int c = 16 * ks + 2 * q;
            uint32_t bh0a = lds_pair(sm + SM_WHI, gA, c,     W_PITCH);
            uint32_t bh0b = lds_pair(sm + SM_WHI, gA, c + 8, W_PITCH);
            uint32_t bh1a = lds_pair(sm + SM_WHI, gB, c,     W_PITCH);
            uint32_t bh1b = lds_pair(sm + SM_WHI, gB, c + 8, W_PITCH);
            mma16816(acc0, ahi[4*ks], ahi[4*ks+1], ahi[4*ks+2], ahi[4*ks+3], bh0a, bh0b);
            mma16816(acc1, ahi[4*ks], ahi[4*ks+1], ahi[4*ks+2], ahi[4*ks+3], bh1a, bh1b);
            mma16816(acc0, alo[4*ks], alo[4*ks+1], alo[4*ks+2], alo[4*ks+3], bh0a, bh0b);
            mma16816(acc1, alo[4*ks], alo[4*ks+1], alo[4*ks+2], alo[4*ks+3], bh1a, bh1b);
            uint32_t bl0a = lds_pair(sm + SM_WLO, gA, c,     W_PITCH);
            uint32_t bl0b = lds_pair(sm + SM_WLO, gA, c + 8, W_PITCH);
            uint32_t bl1a = lds_pair(sm + SM_WLO, gB, c,     W_PITCH);
            uint32_t bl1b = lds_pair(sm + SM_WLO, gB, c + 8, W_PITCH);
            mma16816(acc0, ahi[4*ks], ahi[4*ks+1], ahi[4*ks+2], ahi[4*ks+3], bl0a, bl0b);
            mma16816(acc1, ahi[4*ks], ahi[4*ks+1], ahi[4*ks+2], ahi[4*ks+3], bl1a, bl1b);
        }
        const int col0 = gp * 16 + 2 * q;
        if (v0) {
            *(float2*)(dst + col0)     = make_float2(acc0[0], acc0[1]);
            *(float2*)(dst + col0 + 8) = make_float2(acc1[0], acc1[1]);
        }
        if (v8) {
            *(float2*)(dst8 + col0)     = make_float2(acc0[2], acc0[3]);
            *(float2*)(dst8 + col0 + 8) = make_float2(acc1[2], acc1[3]);
        }
    }
}

// ================= gru: 4-batch fp16 HMMA, single W term ======================
// 64 blocks x 384 threads (12 warps). Warp w owns m-tiles 2w, 2w+1 (rows w*32..+31).
// W fp16 fragments fully register-resident (64 regs). n=8 B cols =
// [h_hi b0..3 | h_lo b0..3] (fp16 split of h). gh = col[b] + col[b+4].
// Gates: threads 0..255 (batch = tid>>6, j-pair = tid&63).
#define GRUT 384

__global__ __launch_bounds__(GRUT, 1)
void gru_hmma_kernel(const float* __restrict__ W_hh,
                     const float* __restrict__ b_ih,
                     const float* __restrict__ b_hh,
                     float* __restrict__ out)
{
    __shared__ uint32_t hbw[8 * 136];        // u64[8][68] view (B fragments)
    __shared__ float ghs[8 * 388];

    const int tid = threadIdx.x;
    const int lane = tid & 31;
    const int wid = tid >> 5;
    const int grp = lane >> 2;
    const int q = lane & 3;
    const int b0 = blockIdx.x * 4;
    const int m0 = wid * 32;                 // rows for this warp's two m-tiles

    // ---- W fragments (fp16), both m-tiles in registers ----
    uint32_t whi0[8][4], whi1[8][4];
    #pragma unroll
    for (int kt = 0; kt < 8; kt++) {
        #pragma unroll
        for (int r = 0; r < 4; r++) {
            int row = m0 + grp + (r & 1) * 8;
            int col = kt * 16 + 2 * q + (r >> 1) * 8;
            float f0 = __ldg(W_hh + (size_t)row * HH + col);
            float f1 = __ldg(W_hh + (size_t)row * HH + col + 1);
            whi0[kt][r] = f16_pack(f0, f1);
            float g0 = __ldg(W_hh + (size_t)(row + 16) * HH + col);
            float g1 = __ldg(W_hh + (size_t)(row + 16) * HH + col + 1);
            whi1[kt][r] = f16_pack(g0, g1);
        }
    }
    // h0 = 0
    for (int idx = tid; idx < 8 * 136; idx += GRUT) {
        hbw[idx] = 0u;
    }

    // ---- gate-role setup (threads 0..255) ----
    const bool is_gate = (tid < 256);
    const int gb = (tid >> 6) & 3;           // batch 0..3
    const int jp = tid & 63;
    const int j = 2 * jp;
    const int ktj = jp >> 3, uj = jp & 7;
    const int slot = (uj < 4) ? (2 * (ktj * 8 + uj)) : (2 * (ktj * 8 + (uj - 4)) + 1);
    const int hi_word = gb * 136 + slot;
    const int lo_word = (gb + 4) * 136 + slot;

    float br0 = 0.f, br1 = 0.f, bz0 = 0.f, bz1 = 0.f;
    float bin0 = 0.f, bin1 = 0.f, bhn0 = 0.f, bhn1 = 0.f;
    float hj = 0.0f, hj1 = 0.0f;
    const float* gxp = g_gx + ((size_t)(b0 + gb) * TT) * GG + j;
    float2 cr = make_float2(0.f, 0.f), cz = cr, cn = cr;
    if (is_gate) {
        br0 = b_ih[j] + b_hh[j];
        br1 = b_ih[j + 1] + b_hh[j + 1];
        bz0 = b_ih[HH + j] + b_hh[HH + j];
        bz1 = b_ih[HH + j + 1] + b_hh[HH + j + 1];
        bin0 = b_ih[2 * HH + j];     bhn0 = b_hh[2 * HH + j];
        bin1 = b_ih[2 * HH + j + 1]; bhn1 = b_hh[2 * HH + j + 1];
        cr = __ldg((const float2*)(gxp));
        cz = __ldg((const float2*)(gxp + HH));
        cn = __ldg((const float2*)(gxp + 2 * HH));
    }
    __syncthreads();

    const unsigned long long* hb64 = (const unsigned long long*)hbw;

    for (int t = 0; t < TT; t++) {
        // prefetch next step's gx (in flight during mma phase)
        float2 nr, nz, nn;
        if (is_gate) {
            const size_t tn = (t + 1 < TT) ? (size_t)(t + 1) : (size_t)t;
            const float* pn = gxp + tn * GG;
            nr = __ldg((const float2*)(pn));
            nz = __ldg((const float2*)(pn + HH));
            nn = __ldg((const float2*)(pn + 2 * HH));
        }

        // ---- mma: 2 m-tiles x 8 kt, single fp16 term ----
        {
            float C0[4] = {0.f, 0.f, 0.f, 0.f};
            float C1[4] = {0.f, 0.f, 0.f, 0.f};
            #pragma unroll
            for (int kt = 0; kt < 8; kt++) {
                unsigned long long bb = hb64[grp * 68 + kt * 8 + q];
                uint32_t bv0 = (uint32_t)bb;
                uint32_t bv1 = (uint32_t)(bb >> 32);
                mma16816h(C0, whi0[kt][0], whi0[kt][1], whi0[kt][2], whi0[kt][3], bv0, bv1);
                mma16816h(C1, whi1[kt][0], whi1[kt][1], whi1[kt][2], whi1[kt][3], bv0, bv1);
            }
            ghs[(2 * q)     * 388 + m0 + grp]          = C0[0];
            ghs[(2 * q + 1) * 388 + m0 + grp]          = C0[1];
            ghs[(2 * q)     * 388 + m0 + grp + 8]      = C0[2];
            ghs[(2 * q + 1) * 388 + m0 + grp + 8]      = C0[3];
            ghs[(2 * q)     * 388 + m0 + 16 + grp]     = C1[0];
            ghs[(2 * q + 1) * 388 + m0 + 16 + grp]     = C1[1];
            ghs[(2 * q)     * 388 + m0 + 16 + grp + 8] = C1[2];
            ghs[(2 * q + 1) * 388 + m0 + 16 + grp + 8] = C1[3];
        }
        __syncthreads();

        // ---- gates: gh = col[gb] + col[gb+4] ----
        if (is_gate) {
            const float* gA = &ghs[gb * 388];
            const float* gB = &ghs[(gb + 4) * 388];
            float2 ra = *(const float2*)(gA + j);
            float2 rb = *(const float2*)(gB + j);
            float2 za = *(const float2*)(gA + HH + j);
            float2 zb = *(const float2*)(gB + HH + j);
            float2 na = *(const float2*)(gA + 2 * HH + j);
            float2 nb = *(const float2*)(gB + 2 * HH + j);
            float r0 = fast_sigmoid(cr.x + br0 + ra.x + rb.x);
            float r1 = fast_sigmoid(cr.y + br1 + ra.y + rb.y);
            float z0 = fast_sigmoid(cz.x + bz0 + za.x + zb.x);
            float z1 = fast_sigmoid(cz.y + bz1 + za.y + zb.y);
            float n0 = fast_tanh(cn.x + bin0 + r0 * (na.x + nb.x + bhn0));
            float n1 = fast_tanh(cn.y + bin1 + r1 * (na.y + nb.y + bhn1));
            hj  = (1.0f - z0) * n0 + z0 * hj;
            hj1 = (1.0f - z1) * n1 + z1 * hj1;
            hbw[hi_word] = f16_pack(hj, hj1);
            hbw[lo_word] = f16_lo_pack(hj, hj1);
            cr = nr; cz = nz; cn = nn;
        }
        __syncthreads();
    }

    if (is_gate) {
        *(float2*)(out + (size_t)(b0 + gb) * HH + j) = make_float2(hj, hj1);
    }
}

// ================= launch =================
extern "C" void kernel_launch(void* const* d_in, const int* in_sizes, int n_in,
                              void* d_out, int out_size)
{
    const float* x    = (const float*)d_in[0];
    const float* W_ih = (const float*)d_in[1];
    const float* W_hh = (const float*)d_in[2];
    const float* b_ih = (const float*)d_in[3];
    const float* b_hh = (const float*)d_in[4];
    float* out = (float*)d_out;

    cudaFuncSetAttribute(gx_hmma_kernel,
                         cudaFuncAttributeMaxDynamicSharedMemorySize, GX_SMEM);

    prep_kernel<<<dim3(8, BB), PREP_THREADS>>>(x);
    gx_hmma_kernel<<<dim3(16, BB), GXT, GX_SMEM>>>(W_ih);
    gru_hmma_kernel<<<BB / 4, GRUT>>>(W_hh, b_ih, b_hh, out);
}

// round 10
// speedup vs baseline: 1.9103x; 1.0049x over previous
#include <cuda_runtime.h>
#include <cuda_bf16.h>
#include <cuda_fp16.h>
#include <cstdint>

#define BB 256
#define MM 80
#define TT 1000
#define HH 128
#define GG 384
#define TPAD 1024

// ---------------- device scratch ----------------
__device__ float g_gx[(size_t)BB * TT * GG];                // 393 MB
__device__ __nv_bfloat16 g_xhi[(size_t)BB * TPAD * MM];     // 42 MB
__device__ __nv_bfloat16 g_xlo[(size_t)BB * TPAD * MM];     // 42 MB

// ---------------- helpers ----------------
__device__ __forceinline__ float fast_sigmoid(float x) {
    float e = __expf(-x);
    return __fdividef(1.0f, 1.0f + e);
}
__device__ __forceinline__ float fast_tanh(float x) {
    float ax = fabsf(x);
    float e = __expf(-2.0f * ax);
    float t = __fdividef(1.0f - e, 1.0f + e);
    return copysignf(t, x);
}
__device__ __forceinline__ void cp16(uint32_t saddr, const void* g) {
    asm volatile("cp.async.cg.shared.global [%0], [%1], 16;" :: "r"(saddr), "l"(g));
}
__device__ __forceinline__ void cp_commit() { asm volatile("cp.async.commit_group;" ::: "memory"); }
__device__ __forceinline__ void cp_wait0()  { asm volatile("cp.async.wait_group 0;" ::: "memory"); }
__device__ __forceinline__ uint32_t smem_u32(const void* p) {
    uint32_t a;
    asm("{ .reg .u64 t; cvta.to.shared.u64 t, %1; cvt.u32.u64 %0, t; }" : "=r"(a) : "l"(p));
    return a;
}
// bf16 mma (gx kernel)
__device__ __forceinline__ void mma16816(float* c, uint32_t a0, uint32_t a1,
                                         uint32_t a2, uint32_t a3,
                                         uint32_t b0, uint32_t b1) {
    asm("mma.sync.aligned.m16n8k16.row.col.f32.bf16.bf16.f32 "
        "{%0,%1,%2,%3}, {%4,%5,%6,%7}, {%8,%9}, {%0,%1,%2,%3};"
        : "+f"(c[0]), "+f"(c[1]), "+f"(c[2]), "+f"(c[3])
        : "r"(a0), "r"(a1), "r"(a2), "r"(a3), "r"(b0), "r"(b1));
}
// fp16 mma (gru kernel)
__device__ __forceinline__ void mma16816h(float* c, uint32_t a0, uint32_t a1,
                                          uint32_t a2, uint32_t a3,
                                          uint32_t b0, uint32_t b1) {
    asm("mma.sync.aligned.m16n8k16.row.col.f32.f16.f16.f32 "
        "{%0,%1,%2,%3}, {%4,%5,%6,%7}, {%8,%9}, {%0,%1,%2,%3};"
        : "+f"(c[0]), "+f"(c[1]), "+f"(c[2]), "+f"(c[3])
        : "r"(a0), "r"(a1), "r"(a2), "r"(a3), "r"(b0), "r"(b1));
}
__device__ __forceinline__ uint32_t f16_pack(float a, float b) {
    __half2 p = __floats2half2_rn(a, b);
    return reinterpret_cast<uint32_t&>(p);
}
__device__ __forceinline__ uint32_t f16_lo_pack(float a, float b) {
    float ra = a - __half2float(__float2half_rn(a));
    float rb = b - __half2float(__float2half_rn(b));
    return f16_pack(ra, rb);
}

// ================= prep: transpose + bf16 split =================
#define PREP_THREADS 256
__global__ __launch_bounds__(PREP_THREADS)
void prep_kernel(const float* __restrict__ x)
{
    __shared__ float xs[MM][129];
    const int b = blockIdx.y, t0 = blockIdx.x * 128;
    const int tid = threadIdx.x;

    for (int idx = tid; idx < MM * 128; idx += PREP_THREADS) {
        int m = idx >> 7, j = idx & 127;
        int t = t0 + j;
        xs[m][j] = (t < TT) ? x[((size_t)b * MM + m) * TT + t] : 0.0f;
    }
    __syncthreads();

    for (int idx = tid; idx < 128 * 10; idx += PREP_THREADS) {
        int j = idx / 10, mv = idx % 10;
        int m0 = mv * 8;
        __align__(16) __nv_bfloat16 hi[8];
        __align__(16) __nv_bfloat16 lo[8];
        #pragma unroll
        for (int u = 0; u < 8; u++) {
            float v = xs[m0 + u][j];
            __nv_bfloat16 h = __float2bfloat16(v);
            hi[u] = h;
            lo[u] = __float2bfloat16(v - __bfloat162float(h));
        }
        size_t off = ((size_t)b * TPAD + t0 + j) * MM + m0;
        *(uint4*)(g_xhi + off) = *(const uint4*)hi;
        *(uint4*)(g_xlo + off) = *(const uint4*)lo;
    }
}

// ================= gx via mma.sync HMMA (split-bf16, 3 terms) =================
#define GXT 256
#define A_PITCH 88
#define W_PITCH 84
#define SM_AHI 0
#define SM_ALO (128 * A_PITCH * 2)
#define SM_WHI (SM_ALO + 128 * A_PITCH * 2)
#define SM_WLO (SM_WHI + 192 * W_PITCH * 2)
#define GX_SMEM (SM_WLO + 192 * W_PITCH * 2)

__device__ __forceinline__ uint32_t lds_pair(const char* base, int row, int col, int pitch) {
    return *(const uint32_t*)(base + (size_t)(row * pitch + col) * 2);
}

__global__ __launch_bounds__(GXT)
void gx_hmma_kernel(const float* __restrict__ W_ih)
{
    extern __shared__ char sm[];
    const int tid = threadIdx.x;
    const int lane = tid & 31;
    const int w = tid >> 5;
    const int grp = lane >> 2;
    const int q = lane & 3;
    const int tt = blockIdx.x >> 1;
    const int ghalf = blockIdx.x & 1;
    const int gbase = ghalf * 192;
    const int b = blockIdx.y;
    const uint32_t sb = smem_u32(sm);

    for (int i = tid; i < 2560; i += GXT) {
        int split = i / 1280;
        int rem = i - split * 1280;
        int row = rem / 10, ch = rem - row * 10;
        uint32_t dst = sb + (split ? SM_ALO : SM_AHI) + row * (A_PITCH * 2) + ch * 16;
        const __nv_bfloat16* src = (split ? g_xlo : g_xhi)
            + ((size_t)b * TPAD + tt * 128 + row) * MM + ch * 8;
        cp16(dst, src);
    }
    cp_commit();

    for (int i = tid; i < 192 * MM; i += GXT) {
        int g = i / MM, m = i - g * MM;
        float v = W_ih[(size_t)(gbase + g) * MM + m];
        __nv_bfloat16 h = __float2bfloat16(v);
        __nv_bfloat16 l = __float2bfloat16(v - __bfloat162float(h));
        *(__nv_bfloat16*)(sm + SM_WHI + (size_t)(g * W_PITCH + m) * 2) = h;
        *(__nv_bfloat16*)(sm + SM_WLO + (size_t)(g * W_PITCH + m) * 2) = l;
    }
    cp_wait0();
    __syncthreads();

    const int r0 = w * 16 + grp;
    uint32_t ahi[20], alo[20];
    #pragma unroll
    for (int ks = 0; ks < 5; ks++) {
        int c = 16 * ks + 2 * q;
        ahi[4 * ks + 0] = lds_pair(sm + SM_AHI, r0,     c,     A_PITCH);
        ahi[4 * ks + 1] = lds_pair(sm + SM_AHI, r0 + 8, c,     A_PITCH);
        ahi[4 * ks + 2] = lds_pair(sm + SM_AHI, r0,     c + 8, A_PITCH);
        ahi[4 * ks + 3] = lds_pair(sm + SM_AHI, r0 + 8, c + 8, A_PITCH);
        alo[4 * ks + 0] = lds_pair(sm + SM_ALO, r0,     c,     A_PITCH);
        alo[4 * ks + 1] = lds_pair(sm + SM_ALO, r0 + 8, c,     A_PITCH);
        alo[4 * ks + 2] = lds_pair(sm + SM_ALO, r0,     c + 8, A_PITCH);
        alo[4 * ks + 3] = lds_pair(sm + SM_ALO, r0 + 8, c + 8, A_PITCH);
    }

    const int trow = tt * 128 + w * 16 + grp;
    float* dst = g_gx + ((size_t)b * TT + trow) * GG + gbase;
    float* dst8 = dst + 8 * GG;
    const bool v0 = (trow < TT);
    const bool v8 = (trow + 8 < TT);

    for (int gp = 0; gp < 12; gp++) {
        float acc0[4] = {0.f, 0.f, 0.f, 0.f};
        float acc1[4] = {0.f, 0.f, 0.f, 0.f};
        const int gA = gp * 16 + grp;
        const int gB = gp * 16 + 8 + grp;
        #pragma unroll
        for (int ks = 0; ks < 5; ks++) {
            int c = 16 * ks + 2 * q;
            uint32_t bh0a = lds_pair(sm + SM_WHI, gA, c,     W_PITCH);
            uint32_t bh0b = lds_pair(sm + SM_WHI, gA, c + 8, W_PITCH);
            uint32_t bh1a = lds_pair(sm + SM_WHI, gB, c,     W_PITCH);
            uint32_t bh1b = lds_pair(sm + SM_WHI, gB, c + 8, W_PITCH);
            mma16816(acc0, ahi[4*ks], ahi[4*ks+1], ahi[4*ks+2], ahi[4*ks+3], bh0a, bh0b);
            mma16816(acc1, ahi[4*ks], ahi[4*ks+1], ahi[4*ks+2], ahi[4*ks+3], bh1a, bh1b);
            mma16816(acc0, alo[4*ks], alo[4*ks+1], alo[4*ks+2], alo[4*ks+3], bh0a, bh0b);
            mma16816(acc1, alo[4*ks], alo[4*ks+1], alo[4*ks+2], alo[4*ks+3], bh1a, bh1b);
            uint32_t bl0a = lds_pair(sm + SM_WLO, gA, c,     W_PITCH);
            uint32_t bl0b = lds_pair(sm + SM_WLO, gA, c + 8, W_PITCH);
            uint32_t bl1a = lds_pair(sm + SM_WLO, gB, c,     W_PITCH);
            uint32_t bl1b = lds_pair(sm + SM_WLO, gB, c + 8, W_PITCH);
            mma16816(acc0, ahi[4*ks], ahi[4*ks+1], ahi[4*ks+2], ahi[4*ks+3], bl0a, bl0b);
            mma16816(acc1, ahi[4*ks], ahi[4*ks+1], ahi[4*ks+2], ahi[4*ks+3], bl1a, bl1b);
        }
        const int col0 = gp * 16 + 2 * q;
        if (v0) {
            *(float2*)(dst + col0)     = make_float2(acc0[0], acc0[1]);
            *(float2*)(dst + col0 + 8) = make_float2(acc1[0], acc1[1]);
        }
        if (v8) {
            *(float2*)(dst8 + col0)     = make_float2(acc0[2], acc0[3]);
            *(float2*)(dst8 + col0 + 8) = make_float2(acc1[2], acc1[3]);
        }
    }
}

// ================= gru: 4-batch fp16 HMMA, single W term ======================
// 64 blocks x 384 threads (12 warps). Warp w owns m-tiles 2w, 2w+1 (rows w*32..+31).
// W fp16 fragments fully register-resident (64 regs). n=8 B cols =
// [h_hi b0..3 | h_lo b0..3] (fp16 split of h). gh = col[b] + col[b+4].
// Gates: threads 0..255 (batch = tid>>6, j-pair = tid&63).
#define GRUT 384

__global__ __launch_bounds__(GRUT, 1)
void gru_hmma_kernel(const float* __restrict__ W_hh,
                     const float* __restrict__ b_ih,
                     const float* __restrict__ b_hh,
                     float* __restrict__ out)
{
    __shared__ uint32_t hbw[8 * 136];        // u64[8][68] view (B fragments)
    __shared__ float ghs[8 * 388];

    const int tid = threadIdx.x;
    const int lane = tid & 31;
    const int wid = tid >> 5;
    const int grp = lane >> 2;
    const int q = lane & 3;
    const int b0 = blockIdx.x * 4;
    const int m0 = wid * 32;                 // rows for this warp's two m-tiles

    // ---- W fragments (fp16), both m-tiles in registers ----
    uint32_t whi0[8][4], whi1[8][4];
    #pragma unroll
    for (int kt = 0; kt < 8; kt++) {
        #pragma unroll
        for (int r = 0; r < 4; r++) {
            int row = m0 + grp + (r & 1) * 8;
            int col = kt * 16 + 2 * q + (r >> 1) * 8;
            float f0 = __ldg(W_hh + (size_t)row * HH + col);
            float f1 = __ldg(W_hh + (size_t)row * HH + col + 1);
            whi0[kt][r] = f16_pack(f0, f1);
            float g0 = __ldg(W_hh + (size_t)(row + 16) * HH + col);
            float g1 = __ldg(W_hh + (size_t)(row + 16) * HH + col + 1);
            whi1[kt][r] = f16_pack(g0, g1);
        }
    }
    // h0 = 0
    for (int idx = tid; idx < 8 * 136; idx += GRUT) {
        hbw[idx] = 0u;
    }

    // ---- gate-role setup (threads 0..255) ----
    const bool is_gate = (tid < 256);
    const int gb = (tid >> 6) & 3;           // batch 0..3
    const int jp = tid & 63;
    const int j = 2 * jp;
    const int ktj = jp >> 3, uj = jp & 7;
    const int slot = (uj < 4) ? (2 * (ktj * 8 + uj)) : (2 * (ktj * 8 + (uj - 4)) + 1);
    const int hi_word = gb * 136 + slot;
    const int lo_word = (gb + 4) * 136 + slot;

    float br0 = 0.f, br1 = 0.f, bz0 = 0.f, bz1 = 0.f;
    float bin0 = 0.f, bin1 = 0.f, bhn0 = 0.f, bhn1 = 0.f;
    float hj = 0.0f, hj1 = 0.0f;
    const float* gxp = g_gx + ((size_t)(b0 + gb) * TT) * GG + j;
    float2 cr = make_float2(0.f, 0.f), cz = cr, cn = cr;
    if (is_gate) {
        br0 = b_ih[j] + b_hh[j];
        br1 = b_ih[j + 1] + b_hh[j + 1];
        bz0 = b_ih[HH + j] + b_hh[HH + j];
        bz1 = b_ih[HH + j + 1] + b_hh[HH + j + 1];
        bin0 = b_ih[2 * HH + j];     bhn0 = b_hh[2 * HH + j];
        bin1 = b_ih[2 * HH + j + 1]; bhn1 = b_hh[2 * HH + j + 1];
        cr = __ldg((const float2*)(gxp));
        cz = __ldg((const float2*)(gxp + HH));
        cn = __ldg((const float2*)(gxp + 2 * HH));
    }
    __syncthreads();

    const unsigned long long* hb64 = (const unsigned long long*)hbw;

    for (int t = 0; t < TT; t++) {
        // prefetch next step's gx (in flight during mma phase)
        float2 nr, nz, nn;
        if (is_gate) {
            const size_t tn = (t + 1 < TT) ? (size_t)(t + 1) : (size_t)t;
            const float* pn = gxp + tn * GG;
            nr = __ldg((const float2*)(pn));
            nz = __ldg((const float2*)(pn + HH));
            nn = __ldg((const float2*)(pn + 2 * HH));
        }

        // ---- mma: 2 m-tiles x 8 kt, single fp16 term ----
        {
            float C0[4] = {0.f, 0.f, 0.f, 0.f};
            float C1[4] = {0.f, 0.f, 0.f, 0.f};
            #pragma unroll
            for (int kt = 0; kt < 8; kt++) {
                unsigned long long bb = hb64[grp * 68 + kt * 8 + q];
                uint32_t bv0 = (uint32_t)bb;
                uint32_t bv1 = (uint32_t)(bb >> 32);
                mma16816h(C0, whi0[kt][0], whi0[kt][1], whi0[kt][2], whi0[kt][3], bv0, bv1);
                mma16816h(C1, whi1[kt][0], whi1[kt][1], whi1[kt][2], whi1[kt][3], bv0, bv1);
            }
            ghs[(2 * q)     * 388 + m0 + grp]          = C0[0];
            ghs[(2 * q + 1) * 388 + m0 + grp]          = C0[1];
            ghs[(2 * q)     * 388 + m0 + grp + 8]      = C0[2];
            ghs[(2 * q + 1) * 388 + m0 + grp + 8]      = C0[3];
            ghs[(2 * q)     * 388 + m0 + 16 + grp]     = C1[0];
            ghs[(2 * q + 1) * 388 + m0 + 16 + grp]     = C1[1];
            ghs[(2 * q)     * 388 + m0 + 16 + grp + 8] = C1[2];
            ghs[(2 * q + 1) * 388 + m0 + 16 + grp + 8] = C1[3];
        }
        __syncthreads();

        // ---- gates: gh = col[gb] + col[gb+4] ----
        if (is_gate) {
            const float* gA = &ghs[gb * 388];
            const float* gB = &ghs[(gb + 4) * 388];
            float2 ra = *(const float2*)(gA + j);
            float2 rb = *(const float2*)(gB + j);
            float2 za = *(const float2*)(gA + HH + j);
            float2 zb = *(const float2*)(gB + HH + j);
            float2 na = *(const float2*)(gA + 2 * HH + j);
            float2 nb = *(const float2*)(gB + 2 * HH + j);
            float r0 = fast_sigmoid(cr.x + br0 + ra.x + rb.x);
            float r1 = fast_sigmoid(cr.y + br1 + ra.y + rb.y);
            float z0 = fast_sigmoid(cz.x + bz0 + za.x + zb.x);
            float z1 = fast_sigmoid(cz.y + bz1 + za.y + zb.y);
            float n0 = fast_tanh(cn.x + bin0 + r0 * (na.x + nb.x + bhn0));
            float n1 = fast_tanh(cn.y + bin1 + r1 * (na.y + nb.y + bhn1));
            hj  = (1.0f - z0) * n0 + z0 * hj;
            hj1 = (1.0f - z1) * n1 + z1 * hj1;
            hbw[hi_word] = f16_pack(hj, hj1);
            hbw[lo_word] = f16_lo_pack(hj, hj1);
            cr = nr; cz = nz; cn = nn;
        }
        __syncthreads();
    }

    if (is_gate) {
        *(float2*)(out + (size_t)(b0 + gb) * HH + j) = make_float2(hj, hj1);
    }
}

// ================= launch =================
extern "C" void kernel_launch(void* const* d_in, const int* in_sizes, int n_in,
                              void* d_out, int out_size)
{
    const float* x    = (const float*)d_in[0];
    const float* W_ih = (const float*)d_in[1];
    const float* W_hh = (const float*)d_in[2];
    const float* b_ih = (const float*)d_in[3];
    const float* b_hh = (const float*)d_in[4];
    float* out = (float*)d_out;

    cudaFuncSetAttribute(gx_hmma_kernel,
                         cudaFuncAttributeMaxDynamicSharedMemorySize, GX_SMEM);

    prep_kernel<<<dim3(8, BB), PREP_THREADS>>>(x);
    gx_hmma_kernel<<<dim3(16, BB), GXT, GX_SMEM>>>(W_ih);
    gru_hmma_kernel<<<BB / 4, GRUT>>>(W_hh, b_ih, b_hh, out);
}